// round 16
// baseline (speedup 1.0000x reference)
#include <cuda_runtime.h>
#include <cstdint>

#define DIM     4096
#define NEXP    64
#define BM      128
#define BK      32
#define NITER   (DIM / BK)       // 128
#define THREADS 256
#define APAD    36               // row stride (floats): 144B, 16B-aligned, 4-bank shift/row
#define ASZ     (BM * APAD)      // 4608 floats
#define BSZ     (NEXP * APAD)    // 2304 floats
#define STAGEF  (ASZ + BSZ)      // 6912 floats = 27648 B
#define NSTAGE  4
#define LPAD    68               // logits overlay row stride (16B-aligned)
#define DYN_SMEM (NSTAGE * STAGEF * 4)   // 110592 B

// ---------------- helpers ----------------
__device__ __forceinline__ uint32_t sptr(const void* p) {
    return (uint32_t)__cvta_generic_to_shared(p);
}
__device__ __forceinline__ void cpa16(uint32_t d, const float* s) {
    asm volatile("cp.async.cg.shared.global [%0], [%1], 16;" :: "r"(d), "l"(s));
}
__device__ __forceinline__ void cpc()  { asm volatile("cp.async.commit_group;" ::: "memory"); }
__device__ __forceinline__ void cpw2() { asm volatile("cp.async.wait_group 2;" ::: "memory"); }

__device__ __forceinline__ uint32_t tfhi(float v) {
    uint32_t r; asm("cvt.rna.tf32.f32 %0, %1;" : "=r"(r) : "f"(v)); return r;
}
// 3-term split: v = hi + lo (each exactly representable in tf32)
__device__ __forceinline__ void split(float v, uint32_t& h, uint32_t& l) {
    h = tfhi(v);
    l = tfhi(v - __uint_as_float(h));
}
__device__ __forceinline__ void mma8(float* d, const uint32_t* a, const uint32_t* b) {
    asm volatile(
        "mma.sync.aligned.m16n8k8.row.col.f32.tf32.tf32.f32 "
        "{%0,%1,%2,%3}, {%4,%5,%6,%7}, {%8,%9}, {%0,%1,%2,%3};"
        : "+f"(d[0]), "+f"(d[1]), "+f"(d[2]), "+f"(d[3])
        : "r"(a[0]), "r"(a[1]), "r"(a[2]), "r"(a[3]), "r"(b[0]), "r"(b[1]));
}

__device__ __forceinline__ void load_stage(float* sm, int buf, const float* x,
                                           const float* W, int m0, int k0, int tid) {
    float* As = sm + buf * STAGEF;
    float* Bs = As + ASZ;
#pragma unroll
    for (int p = 0; p < 4; p++) {                 // A: 128 rows x 128B
        int idx = tid + p * THREADS;
        int row = idx >> 3, c = idx & 7;
        cpa16(sptr(As + row * APAD + c * 4),
              x + (size_t)(m0 + row) * DIM + k0 + c * 4);
    }
#pragma unroll
    for (int p = 0; p < 2; p++) {                 // B: 64 rows x 128B
        int idx = tid + p * THREADS;
        int row = idx >> 3, c = idx & 7;
        cpa16(sptr(Bs + row * APAD + c * 4),
              W + (size_t)row * DIM + k0 + c * 4);
    }
}

// ---------------- fused gate kernel ----------------
__global__ void __launch_bounds__(THREADS, 1)
gate_mma(const float* __restrict__ x, const float* __restrict__ W,
         float* __restrict__ out, int N, int with_idx)
{
    extern __shared__ __align__(16) float sm[];
    const int tid  = threadIdx.x;
    const int wid  = tid >> 5;
    const int lane = tid & 31;
    const int gid  = lane >> 2;          // 0..7
    const int tig  = lane & 3;           // 0..3
    const int wm   = (wid & 3) * 32;     // warp M offset (4 M-warps)
    const int wn   = (wid >> 2) * 32;    // warp N offset (2 N-warps)
    const int m0   = blockIdx.x * BM;

    float acc[2][4][4];
#pragma unroll
    for (int mt = 0; mt < 2; mt++)
#pragma unroll
        for (int nt = 0; nt < 4; nt++)
#pragma unroll
            for (int q = 0; q < 4; q++) acc[mt][nt][q] = 0.0f;

    // prologue: stages 0..2 in flight
#pragma unroll
    for (int s = 0; s < NSTAGE - 1; s++) {
        load_stage(sm, s, x, W, m0, s * BK, tid);
        cpc();
    }

    for (int it = 0; it < NITER; it++) {
        const int buf = it & (NSTAGE - 1);
        cpw2();                       // stage `it` complete (<=2 groups pending)
        __syncthreads();

        if (it + NSTAGE - 1 < NITER)
            load_stage(sm, (it + NSTAGE - 1) & (NSTAGE - 1), x, W, m0,
                       (it + NSTAGE - 1) * BK, tid);
        cpc();                        // one group per iteration (may be empty)

        const float* As = sm + buf * STAGEF;
        const float* Bs = As + ASZ;
        const float* pa = As + (wm + gid) * APAD;
        const float* pb = Bs + (wn + gid) * APAD;

#pragma unroll
        for (int ks = 0; ks < 4; ks++) {          // 4 x k8 per BK=32
            const int k = ks * 8 + tig;
            uint32_t ah[2][4], al[2][4], bh[4][2], bl[4][2];
#pragma unroll
            for (int mt = 0; mt < 2; mt++) {
                const float* q = pa + mt * 16 * APAD;
                split(q[k],                ah[mt][0], al[mt][0]);
                split(q[8 * APAD + k],     ah[mt][1], al[mt][1]);
                split(q[k + 4],            ah[mt][2], al[mt][2]);
                split(q[8 * APAD + k + 4], ah[mt][3], al[mt][3]);
            }
#pragma unroll
            for (int nt = 0; nt < 4; nt++) {
                const float* q = pb + nt * 8 * APAD;
                split(q[k],     bh[nt][0], bl[nt][0]);
                split(q[k + 4], bh[nt][1], bl[nt][1]);
            }
            // 3 terms, each swept across all 8 acc tiles (dependency distance >= 8 mma)
#pragma unroll
            for (int mt = 0; mt < 2; mt++)
#pragma unroll
                for (int nt = 0; nt < 4; nt++) mma8(acc[mt][nt], ah[mt], bh[nt]);
#pragma unroll
            for (int mt = 0; mt < 2; mt++)
#pragma unroll
                for (int nt = 0; nt < 4; nt++) mma8(acc[mt][nt], ah[mt], bl[nt]);
#pragma unroll
            for (int mt = 0; mt < 2; mt++)
#pragma unroll
                for (int nt = 0; nt < 4; nt++) mma8(acc[mt][nt], al[mt], bh[nt]);
        }
    }

    // ---------------- epilogue: logits -> top-2 -> softmax -> scatter ----------------
    __syncthreads();                  // all stage reads done before overlay
    float* ls = sm;                   // overlay: [128][LPAD] logits

#pragma unroll
    for (int mt = 0; mt < 2; mt++)
#pragma unroll
        for (int nt = 0; nt < 4; nt++) {
            const int r = wm + mt * 16 + gid;
            const int c = wn + nt * 8 + tig * 2;
            *(float2*)(ls + r * LPAD + c)       = make_float2(acc[mt][nt][0], acc[mt][nt][1]);
            *(float2*)(ls + (r + 8) * LPAD + c) = make_float2(acc[mt][nt][2], acc[mt][nt][3]);
        }
    __syncthreads();

    if (tid < BM) {
        float* row = ls + tid * LPAD;
        float v1 = -3.4e38f, v2 = -3.4e38f;
        int   i1 = 0, i2 = 0;
#pragma unroll
        for (int j = 0; j < NEXP; j++) {          // ties -> lower index (JAX top_k)
            float v = row[j];
            if (v > v1)      { v2 = v1; i2 = i1; v1 = v; i1 = j; }
            else if (v > v2) { v2 = v;  i2 = j; }
        }
        const float e2 = expf(v2 - v1);           // v1 >= v2: stable
        const float ss = 1.0f / (1.0f + e2);
        const float w1 = ss, w2 = e2 * ss;
#pragma unroll
        for (int j = 0; j < NEXP; j++) row[j] = 0.0f;
        row[i1] = w1;
        row[i2] = w2;
        if (with_idx) {
            *(float2*)(out + (size_t)N * NEXP + (size_t)(m0 + tid) * 2) =
                make_float2((float)i1, (float)i2);
        }
    }
    __syncthreads();

    // coalesced copy of the 128x64 weight block
    for (int q = tid; q < BM * NEXP / 4; q += THREADS) {
        const int i = q * 4;
        const int r = i >> 6, c = i & 63;
        float4 v = *(const float4*)(ls + r * LPAD + c);
        *(float4*)(out + (size_t)m0 * NEXP + i) = v;
    }
}

// ---------------- launch ----------------
extern "C" void kernel_launch(void* const* d_in, const int* in_sizes, int n_in,
                              void* d_out, int out_size) {
    const float* x  = (const float*)d_in[0];   // [N, 4096]
    const float* Wm = (const float*)d_in[1];   // [64, 4096]
    const int N = in_sizes[0] / DIM;           // 16384

    cudaFuncSetAttribute(gate_mma, cudaFuncAttributeMaxDynamicSharedMemorySize,
                         DYN_SMEM);
    const int with_idx = (out_size >= N * NEXP + N * 2) ? 1 : 0;
    gate_mma<<<N / BM, THREADS, DYN_SMEM>>>(x, Wm, (float*)d_out, N, with_idx);
}